// round 16
// baseline (speedup 1.0000x reference)
#include <cuda_runtime.h>
#include <cuda_fp16.h>
#include <cstdint>

#define NB 16
#define NS 2048
#define ND 1024
#define NTH 512
#define KS 64
#define STAGE_B 49152     // A 16K | B 32K
#define OFF_A 0
#define OFF_B 16384
#define OFF_P 147456      // P staging region (64KB), disjoint from 3-buffer ring
#define SMEM_DYN 212992   // 3*48KB ring + 64KB P staging
#define SCALE 0.03125f
#define BPG 8             // batches per group (2 groups)

__device__ int   g_cnt[NB];
__device__ int   g_rows[NB * NS];      // [0,cnt): unmasked rows, [cnt,NS): masked rows
__device__ float g_meanV[NB * ND];
__device__ float g_l[NB * NS];
__device__ __half g_Q[(size_t)NB * NS * ND];
__device__ __half g_K[(size_t)NB * NS * ND];
__device__ __half g_Vt[(size_t)NB * ND * NS];
__device__ __half g_P[(size_t)NB * NS * NS];

// ---------------- helpers ----------------
__device__ __forceinline__ uint32_t smem_u32(const void* p) {
    uint32_t a;
    asm("{ .reg .u64 t; cvta.to.shared.u64 t, %1; cvt.u32.u64 %0, t; }" : "=r"(a) : "l"(p));
    return a;
}
__device__ __forceinline__ uint32_t swz(uint32_t off) { return off ^ ((off >> 3) & 0x70); }

__device__ __forceinline__ void cpa16(uint32_t s, const void* g) {
    asm volatile("cp.async.cg.shared.global [%0], [%1], 16;" :: "r"(s), "l"(g));
}
#define CPA_COMMIT() asm volatile("cp.async.commit_group;" ::: "memory")
#define CPA_WAIT(n)  asm volatile("cp.async.wait_group %0;" :: "n"(n) : "memory")

__device__ __forceinline__ void ldsm4(uint32_t* r, uint32_t a) {
    asm volatile("ldmatrix.sync.aligned.m8n8.x4.shared.b16 {%0,%1,%2,%3}, [%4];"
        : "=r"(r[0]), "=r"(r[1]), "=r"(r[2]), "=r"(r[3]) : "r"(a));
}
__device__ __forceinline__ void mma16816(float* d, const uint32_t* a, const uint32_t* b) {
    asm volatile("mma.sync.aligned.m16n8k16.row.col.f32.f16.f16.f32 "
        "{%0,%1,%2,%3},{%4,%5,%6,%7},{%8,%9},{%0,%1,%2,%3};"
        : "+f"(d[0]), "+f"(d[1]), "+f"(d[2]), "+f"(d[3])
        : "r"(a[0]), "r"(a[1]), "r"(a[2]), "r"(a[3]), "r"(b[0]), "r"(b[1]));
}
__device__ __forceinline__ uint2 half4cvt(float4 f) {
    __half2 h0 = __float22half2_rn(make_float2(f.x, f.y));
    __half2 h1 = __float22half2_rn(make_float2(f.z, f.w));
    uint2 r;
    r.x = *(uint32_t*)&h0; r.y = *(uint32_t*)&h1;
    return r;
}

// ---------------- prep ----------------
__global__ void k_compact(const unsigned char* __restrict__ mask) {
    __shared__ int c0, c1, found;
    if (threadIdx.x == 0) { c0 = 0; c1 = 0; found = 0; }
    __syncthreads();
    for (int i = threadIdx.x; i < 8192; i += blockDim.x)
        if ((i & 3) != 0 && mask[i] != 0) found = 1;
    __syncthreads();
    const int ms = found ? 1 : 4;
    const int b = blockIdx.x;
    for (int i = threadIdx.x; i < NS; i += blockDim.x) {
        if (mask[(size_t)(b * NS + i) * ms]) {
            int p = atomicAdd(&c0, 1);
            g_rows[b * NS + p] = i;
        } else {
            int p = atomicAdd(&c1, 1);
            g_rows[b * NS + NS - 1 - p] = i;
        }
    }
    __syncthreads();
    if (threadIdx.x == 0) g_cnt[b] = c0;
}
// Q + K conversion for one batch group
__global__ void k_prepQK(const float* __restrict__ q, const float* __restrict__ k, int grp) {
    const size_t base = (size_t)grp * BPG * NS * ND;
    const int half = BPG * NS * ND / 1024;                // 16384 blocks per tensor chunk
    int bid = blockIdx.x;
    if (bid < half) {
        size_t i = base + ((size_t)bid * 256 + threadIdx.x) * 4;
        *(uint2*)(g_Q + i) = half4cvt(*(const float4*)(q + i));
    } else {
        size_t i = base + ((size_t)(bid - half) * 256 + threadIdx.x) * 4;
        *(uint2*)(g_K + i) = half4cvt(*(const float4*)(k + i));
    }
}
__global__ void k_prepV(const float* __restrict__ v) {
    __shared__ float t[32][33];
    int vid = blockIdx.x;
    int b = vid >> 11, rem = vid & 2047;
    int d0 = (rem >> 6) * 32, j0 = (rem & 63) * 32;
    int x = threadIdx.x & 31, y = threadIdx.x >> 5;
    const float* src = v + (size_t)b * NS * ND;
#pragma unroll
    for (int i = 0; i < 32; i += 8)
        t[y + i][x] = src[(size_t)(j0 + y + i) * ND + d0 + x];
    __syncthreads();
#pragma unroll
    for (int i = 0; i < 32; i += 8)
        g_Vt[((size_t)b * ND + d0 + y + i) * NS + j0 + x] = __float2half(t[x][y + i]);
}
__global__ void k_meanvt() {
    int row = blockIdx.x * 8 + (threadIdx.x >> 5);
    int lane = threadIdx.x & 31;
    const __half* p = g_Vt + (size_t)row * NS;
    float s = 0.f;
#pragma unroll
    for (int i = 0; i < 16; i++) {
        uint2 u = *(const uint2*)(p + (lane + i * 32) * 4);
        __half2 a = *(__half2*)&u.x, c = *(__half2*)&u.y;
        float2 fa = __half22float2(a), fc = __half22float2(c);
        s += (fa.x + fa.y) + (fc.x + fc.y);
    }
#pragma unroll
    for (int off = 16; off; off >>= 1) s += __shfl_xor_sync(0xffffffffu, s, off);
    if (lane == 0) g_meanV[row] = s * (1.0f / NS);
}
__global__ void k_fill(float* __restrict__ out) {
    int r = blockIdx.x;
    int b = r >> 11, slot = r & 2047;
    if (slot < g_cnt[b]) return;
    int grow = g_rows[b * NS + slot];
    ((float4*)(out + ((size_t)(b * NS + grow)) * ND))[threadIdx.x] =
        ((const float4*)(g_meanV + b * ND))[threadIdx.x];
}

// ---------------- QK + softmax (512 thr, 128x256 tile, fp16, continuous 3-buf ring) ----------------
__global__ void __launch_bounds__(NTH) k_qk(int bbase)
{
    extern __shared__ char sm[];
    __shared__ int rows_s[128];
    __shared__ float l2[4][128];

    const int tid = threadIdx.x;
    const int b = bbase + (blockIdx.x >> 4), qb = blockIdx.x & 15;
    const int cnt = g_cnt[b];
    if (qb * 128 >= cnt) return;

    const int lane = tid & 31, wid = tid >> 5;
    const int mband = wid & 3, nq = wid >> 2;
    const int g = lane >> 2, tp = lane & 3;

    if (tid < 128)
        rows_s[tid] = g_rows[b * NS + qb * 128 + tid];
    __syncthreads();

    const uint32_t smb = smem_u32(sm);
    const int arow0 = mband * 32 + (lane & 15);
    const int aks = lane >> 4;
    const int brow0 = nq * 64 + (lane & 7) + ((lane & 16) >> 1);
    const int bks = (lane >> 3) & 1;
    const size_t bbase_e = (size_t)b * NS;
    const int srow = tid >> 3, sseg = tid & 7;
    float lacc[2][2] = {{0.f, 0.f}, {0.f, 0.f}};
    float s[2][8][4];

#define QK_STAGE(cg_) do { \
        const int dc_ = ((cg_) & 15) * KS; \
        const int j0_ = ((cg_) >> 4) * 256; \
        const uint32_t bp_ = smb + (uint32_t)((cg_) % 3) * STAGE_B; \
        _Pragma("unroll") \
        for (int i_ = 0; i_ < 2; i_++) { \
            int row_ = srow + i_ * 64; \
            size_t e_ = (bbase_e + rows_s[row_]) * ND + dc_ + sseg * 8; \
            cpa16(bp_ + OFF_A + swz((uint32_t)(row_ * 128 + sseg * 16)), g_Q + e_); \
        } \
        _Pragma("unroll") \
        for (int i_ = 0; i_ < 4; i_++) { \
            int row_ = srow + i_ * 64; \
            size_t e_ = (bbase_e + j0_ + row_) * ND + dc_ + sseg * 8; \
            cpa16(bp_ + OFF_B + swz((uint32_t)(row_ * 128 + sseg * 16)), g_K + e_); \
        } \
        CPA_COMMIT(); \
    } while (0)

    QK_STAGE(0);
    QK_STAGE(1);
    for (int cg = 0; cg < 128; cg++) {
        if ((cg & 15) == 0) {
#pragma unroll
            for (int mf = 0; mf < 2; mf++)
#pragma unroll
                for (int nf = 0; nf < 8; nf++)
#pragma unroll
                    for (int i = 0; i < 4; i++) s[mf][nf][i] = 0.f;
        }
        if (cg + 1 < 128) CPA_WAIT(1);
        else CPA_WAIT(0);
        __syncthreads();
        if (cg + 2 < 128) QK_STAGE(cg + 2);
        const uint32_t sb = smb + (uint32_t)(cg % 3) * STAGE_B;
#pragma unroll
        for (int ks = 0; ks < 4; ks++) {
            uint32_t ah[2][4];
#pragma unroll
            for (int mf = 0; mf < 2; mf++)
                ldsm4(ah[mf], sb + OFF_A + swz((uint32_t)((arow0 + mf * 16) * 128 + (2 * ks + aks) * 16)));
#pragma unroll
            for (int nfp = 0; nfp < 4; nfp++) {
                uint32_t bh[4];
                ldsm4(bh, sb + OFF_B + swz((uint32_t)((brow0 + nfp * 16) * 128 + (2 * ks + bks) * 16)));
#pragma unroll
                for (int mf = 0; mf < 2; mf++) {
                    mma16816(s[mf][2 * nfp], ah[mf], bh);
                    mma16816(s[mf][2 * nfp + 1], ah[mf], bh + 2);
                }
            }
        }
        if ((cg & 15) == 15) {
            const int j0 = (cg >> 4) * 256;
#pragma unroll
            for (int mf = 0; mf < 2; mf++) {
                int r0 = mband * 32 + mf * 16 + g, r1 = r0 + 8;
#pragma unroll
                for (int nf = 0; nf < 8; nf++) {
                    int col = nq * 64 + nf * 8 + tp * 2;
                    float p0 = __expf(s[mf][nf][0] * SCALE), p1 = __expf(s[mf][nf][1] * SCALE);
                    float p2 = __expf(s[mf][nf][2] * SCALE), p3 = __expf(s[mf][nf][3] * SCALE);
                    __half2 h01 = __float22half2_rn(make_float2(p0, p1));
                    __half2 h23 = __float22half2_rn(make_float2(p2, p3));
                    float2 r01 = __half22float2(h01), r23 = __half22float2(h23);
                    lacc[mf][0] += r01.x + r01.y;
                    lacc[mf][1] += r23.x + r23.y;
                    uint32_t a0 = OFF_P + ((uint32_t)(r0 * 512 + col * 2) ^ ((r0 & 7) << 4));
                    uint32_t a1 = OFF_P + ((uint32_t)(r1 * 512 + col * 2) ^ ((r1 & 7) << 4));
                    *(uint32_t*)(sm + a0) = *(uint32_t*)&h01;
                    *(uint32_t*)(sm + a1) = *(uint32_t*)&h23;
                }
            }
            __syncthreads();
#pragma unroll
            for (int i = 0; i < 8; i++) {
                int u = i * NTH + tid;
                int r = u >> 5, c = u & 31;
                uint32_t a = OFF_P + ((uint32_t)(r * 512 + c * 16) ^ ((r & 7) << 4));
                size_t e = ((size_t)(b * NS + qb * 128 + r)) * NS + j0 + c * 8;
                *(uint4*)(g_P + e) = *(uint4*)(sm + a);
            }
        }
    }
#undef QK_STAGE
    __syncthreads();
#pragma unroll
    for (int mf = 0; mf < 2; mf++)
#pragma unroll
        for (int h = 0; h < 2; h++) {
            float v = lacc[mf][h];
            v += __shfl_xor_sync(0xffffffffu, v, 1);
            v += __shfl_xor_sync(0xffffffffu, v, 2);
            if (tp == 0) l2[nq][mband * 32 + mf * 16 + h * 8 + g] = v;
        }
    __syncthreads();
    if (tid < 128)
        g_l[b * NS + qb * 128 + tid] = (l2[0][tid] + l2[1][tid]) + (l2[2][tid] + l2[3][tid]);
}

// ---------------- PV (512 thr, 128x256 tile, fp16, 3-buf ring) ----------------
__global__ void __launch_bounds__(NTH) k_pv(float* __restrict__ out, int bbase)
{
    extern __shared__ char sm[];
    __shared__ int rows_s[128];

    const int tid = threadIdx.x;
    const int b = bbase + (blockIdx.x >> 6), qb = (blockIdx.x >> 2) & 15, dt = blockIdx.x & 3;
    const int cnt = g_cnt[b];
    const int d0 = dt * 256;
    if (qb * 128 >= cnt) return;

    const int lane = tid & 31, wid = tid >> 5;
    const int mband = wid & 3, nq = wid >> 2;
    const int g = lane >> 2, tp = lane & 3;

    if (tid < 128)
        rows_s[tid] = g_rows[b * NS + qb * 128 + tid];
    __syncthreads();

    const uint32_t smb = smem_u32(sm);
    const int arow0 = mband * 32 + (lane & 15);
    const int aks = lane >> 4;
    const int brow0 = nq * 64 + (lane & 7) + ((lane & 16) >> 1);
    const int bks = (lane >> 3) & 1;
    const int srow = tid >> 3, sseg = tid & 7;

    float o[2][8][4];
#pragma unroll
    for (int mf = 0; mf < 2; mf++)
#pragma unroll
        for (int nf = 0; nf < 8; nf++)
#pragma unroll
            for (int i = 0; i < 4; i++) o[mf][nf][i] = 0.f;

#define PV_STAGE(jc) do { \
        const uint32_t bp_ = smb + (uint32_t)((jc) % 3) * STAGE_B; \
        _Pragma("unroll") \
        for (int i_ = 0; i_ < 2; i_++) { \
            int row_ = srow + i_ * 64; \
            size_t e_ = ((size_t)(b * NS + qb * 128 + row_)) * NS + (jc) * KS + sseg * 8; \
            cpa16(bp_ + OFF_A + swz((uint32_t)(row_ * 128 + sseg * 16)), g_P + e_); \
        } \
        _Pragma("unroll") \
        for (int i_ = 0; i_ < 4; i_++) { \
            int row_ = srow + i_ * 64; \
            size_t e_ = ((size_t)(b * ND + d0 + row_)) * NS + (jc) * KS + sseg * 8; \
            cpa16(bp_ + OFF_B + swz((uint32_t)(row_ * 128 + sseg * 16)), g_Vt + e_); \
        } \
        CPA_COMMIT(); \
    } while (0)

    PV_STAGE(0);
    PV_STAGE(1);
    for (int jc = 0; jc < NS / KS; jc++) {
        if (jc + 1 < NS / KS) CPA_WAIT(1);
        else CPA_WAIT(0);
        __syncthreads();
        if (jc + 2 < NS / KS) PV_STAGE(jc + 2);
        const uint32_t sb = smb + (uint32_t)(jc % 3) * STAGE_B;
#pragma unroll
        for (int ks = 0; ks < 4; ks++) {
            uint32_t ah[2][4];
#pragma unroll
            for (int mf = 0; mf < 2; mf++)
                ldsm4(ah[mf], sb + OFF_A + swz((uint32_t)((arow0 + mf * 16) * 128 + (2 * ks + aks) * 16)));
#pragma unroll
            for (int nfp = 0; nfp < 4; nfp++) {
                uint32_t bh[4];
                ldsm4(bh, sb + OFF_B + swz((uint32_t)((brow0 + nfp * 16) * 128 + (2 * ks + bks) * 16)));
#pragma unroll
                for (int mf = 0; mf < 2; mf++) {
                    mma16816(o[mf][2 * nfp], ah[mf], bh);
                    mma16816(o[mf][2 * nfp + 1], ah[mf], bh + 2);
                }
            }
        }
    }
#undef PV_STAGE
    __syncthreads();
    float inv[2][2];
#pragma unroll
    for (int mf = 0; mf < 2; mf++)
#pragma unroll
        for (int h = 0; h < 2; h++) {
            int slot = qb * 128 + mband * 32 + mf * 16 + h * 8 + g;
            inv[mf][h] = (slot < cnt) ? (1.0f / g_l[b * NS + slot]) : 0.f;
        }
#pragma unroll
    for (int mf = 0; mf < 2; mf++) {
        int r0 = mband * 32 + mf * 16 + g, r1 = r0 + 8;
#pragma unroll
        for (int nf = 0; nf < 8; nf++) {
            int col = nq * 64 + nf * 8 + tp * 2;
            uint32_t a0 = (uint32_t)(r0 * 1024 + col * 4) ^ ((r0 & 7) << 4);
            uint32_t a1 = (uint32_t)(r1 * 1024 + col * 4) ^ ((r1 & 7) << 4);
            *(float2*)(sm + a0) = make_float2(o[mf][nf][0] * inv[mf][0], o[mf][nf][1] * inv[mf][0]);
            *(float2*)(sm + a1) = make_float2(o[mf][nf][2] * inv[mf][1], o[mf][nf][3] * inv[mf][1]);
        }
    }
    __syncthreads();
#pragma unroll
    for (int i = 0; i < 16; i++) {
        int u = i * NTH + tid, r = u >> 6, seg = u & 63;
        int grow = rows_s[r];
        float4 val;
        if (qb * 128 + r < cnt) {
            uint32_t a = (uint32_t)(r * 1024 + seg * 16) ^ ((r & 7) << 4);
            val = *(float4*)(sm + a);
        } else {
            val = ((const float4*)(g_meanV + b * ND + d0))[seg];
        }
        *(float4*)(out + ((size_t)(b * NS + grow)) * ND + d0 + seg * 4) = val;
    }
}

// ---------------- launch: 2 streams, 2-group software pipeline ----------------
extern "C" void kernel_launch(void* const* d_in, const int* in_sizes, int n_in,
                              void* d_out, int out_size)
{
    const float* q = (const float*)d_in[0];
    const float* k = (const float*)d_in[1];
    const float* v = (const float*)d_in[2];
    const unsigned char* mask = (const unsigned char*)d_in[3];
    float* out = (float*)d_out;

    static cudaStream_t s2 = nullptr;
    static cudaEvent_t evFork, evC, eP0, eP1, eQ0, evV, evD0;
    if (!s2) {
        cudaStreamCreateWithFlags(&s2, cudaStreamNonBlocking);
        cudaEventCreateWithFlags(&evFork, cudaEventDisableTiming);
        cudaEventCreateWithFlags(&evC, cudaEventDisableTiming);
        cudaEventCreateWithFlags(&eP0, cudaEventDisableTiming);
        cudaEventCreateWithFlags(&eP1, cudaEventDisableTiming);
        cudaEventCreateWithFlags(&eQ0, cudaEventDisableTiming);
        cudaEventCreateWithFlags(&evV, cudaEventDisableTiming);
        cudaEventCreateWithFlags(&evD0, cudaEventDisableTiming);
        cudaFuncSetAttribute(k_qk, cudaFuncAttributeMaxDynamicSharedMemorySize, SMEM_DYN);
        cudaFuncSetAttribute(k_pv, cudaFuncAttributeMaxDynamicSharedMemorySize, SMEM_DYN);
    }

    const int prep_blocks = 2 * (BPG * NS * ND / 1024);    // 32768

    // fork
    cudaEventRecord(evFork, 0);
    cudaStreamWaitEvent(s2, evFork, 0);

    // default: prepQK_g0 -> (evC) qk_g0 -> eQ0 -> (eP1) qk_g1 -> (evV) pv_g1
    k_prepQK<<<prep_blocks, 256>>>(q, k, 0);
    cudaEventRecord(eP0, 0);

    // s2: compact -> evC -> (eP0) prepQK_g1 -> eP1 -> prepV -> meanvt -> fill -> evV
    k_compact<<<NB, 256, 0, s2>>>(mask);
    cudaEventRecord(evC, s2);
    cudaStreamWaitEvent(s2, eP0, 0);                       // avoid BW contention with g0 prep
    k_prepQK<<<prep_blocks, 256, 0, s2>>>(q, k, 1);
    cudaEventRecord(eP1, s2);
    k_prepV<<<32768, 256, 0, s2>>>(v);
    k_meanvt<<<NB * ND / 8, 256, 0, s2>>>();
    k_fill<<<NB * NS, 256, 0, s2>>>(out);
    cudaEventRecord(evV, s2);

    cudaStreamWaitEvent(0, evC, 0);
    k_qk<<<BPG * 16, NTH, SMEM_DYN>>>(0);
    cudaEventRecord(eQ0, 0);
    cudaStreamWaitEvent(0, eP1, 0);
    k_qk<<<BPG * 16, NTH, SMEM_DYN>>>(BPG);

    // s2: pv_g0 after fill (in-stream) + qk_g0 (eQ0); co-runs with qk_g1
    cudaStreamWaitEvent(s2, eQ0, 0);
    k_pv<<<BPG * 64, NTH, SMEM_DYN, s2>>>(out, 0);
    cudaEventRecord(evD0, s2);

    // default: pv_g1 after qk_g1 (in-stream) + fill chain (evV); then join pv_g0
    cudaStreamWaitEvent(0, evV, 0);
    k_pv<<<BPG * 64, NTH, SMEM_DYN>>>(out, BPG);
    cudaStreamWaitEvent(0, evD0, 0);
}